// round 6
// baseline (speedup 1.0000x reference)
#include <cuda_runtime.h>

// QuantizedTopKSparsity == out[r,c] = rint( x[r,c] / (max_c |x[r,c]| + 1e-6) )
// (quantized values are in {-1,0,+1}; the top-k mask is an identity on x_q).
//
// Round-6: 2 rows per CTA, 512 threads, ONE barrier for both rows' absmax
// reductions. Each thread issues two independent 256-bit loads (one per row)
// before the barrier -> deeper, smoother DRAM bursts per CTA and half the
// CTAs. Keeps v8 + evict_last/evict_first (measured equal-best).

#define ROW_LEN 4096
#define THREADS 512
#define NWARPS (THREADS / 32)

struct F8 { float a, b, c, d, e, f, g, h; };

__device__ __forceinline__ F8 ld_persist8(const void* p) {
    F8 v;
    asm volatile("ld.global.L2::evict_last.v8.b32 "
                 "{%0,%1,%2,%3,%4,%5,%6,%7}, [%8];"
                 : "=f"(v.a), "=f"(v.b), "=f"(v.c), "=f"(v.d),
                   "=f"(v.e), "=f"(v.f), "=f"(v.g), "=f"(v.h)
                 : "l"(p));
    return v;
}

__device__ __forceinline__ void st_stream8(void* p, const F8& v) {
    asm volatile("st.global.L2::evict_first.v8.b32 "
                 "[%0], {%1,%2,%3,%4,%5,%6,%7,%8};"
                 :: "l"(p),
                    "f"(v.a), "f"(v.b), "f"(v.c), "f"(v.d),
                    "f"(v.e), "f"(v.f), "f"(v.g), "f"(v.h)
                 : "memory");
}

__device__ __forceinline__ float absmax8(const F8& v) {
    float m0 = fmaxf(fmaxf(fabsf(v.a), fabsf(v.b)), fmaxf(fabsf(v.c), fabsf(v.d)));
    float m1 = fmaxf(fmaxf(fabsf(v.e), fabsf(v.f)), fmaxf(fabsf(v.g), fabsf(v.h)));
    return fmaxf(m0, m1);
}

__device__ __forceinline__ F8 quant8(const F8& v, float inv) {
    F8 o;
    o.a = rintf(v.a * inv); o.b = rintf(v.b * inv);
    o.c = rintf(v.c * inv); o.d = rintf(v.d * inv);
    o.e = rintf(v.e * inv); o.f = rintf(v.f * inv);
    o.g = rintf(v.g * inv); o.h = rintf(v.h * inv);
    return o;
}

__global__ __launch_bounds__(THREADS)
void qtopk_kernel(const float* __restrict__ x, float* __restrict__ out, int row_pairs) {
    const int pair = blockIdx.x;
    if (pair >= row_pairs) return;

    const size_t base = (size_t)pair * 2 * ROW_LEN;
    const float* __restrict__ x0 = x + base;
    const float* __restrict__ x1 = x + base + ROW_LEN;
    float* __restrict__ o0 = out + base;
    float* __restrict__ o1 = out + base + ROW_LEN;

    const int t = threadIdx.x;          // 512 threads * 8 floats = 4096 = ROW_LEN

    // Issue both rows' 256-bit loads back-to-back (two DRAM streams in flight).
    F8 v0 = ld_persist8(x0 + t * 8);
    F8 v1 = ld_persist8(x1 + t * 8);

    float m0 = absmax8(v0);
    float m1 = absmax8(v1);

    // Warp reductions for both rows.
#pragma unroll
    for (int o = 16; o > 0; o >>= 1) {
        m0 = fmaxf(m0, __shfl_xor_sync(0xffffffffu, m0, o));
        m1 = fmaxf(m1, __shfl_xor_sync(0xffffffffu, m1, o));
    }

    __shared__ float s0[NWARPS], s1[NWARPS];
    if ((t & 31) == 0) { s0[t >> 5] = m0; s1[t >> 5] = m1; }
    __syncthreads();

    float g0 = s0[0], g1 = s1[0];
#pragma unroll
    for (int w = 1; w < NWARPS; w++) {
        g0 = fmaxf(g0, s0[w]);
        g1 = fmaxf(g1, s1[w]);
    }

    const float inv0 = 1.0f / (g0 + 1e-6f);
    const float inv1 = 1.0f / (g1 + 1e-6f);

    st_stream8(o0 + t * 8, quant8(v0, inv0));
    st_stream8(o1 + t * 8, quant8(v1, inv1));
}

extern "C" void kernel_launch(void* const* d_in, const int* in_sizes, int n_in,
                              void* d_out, int out_size) {
    const float* x = (const float*)d_in[0];
    float* out = (float*)d_out;
    const int rows = in_sizes[0] / ROW_LEN;   // 8192
    qtopk_kernel<<<rows / 2, THREADS>>>(x, out, rows / 2);
}

// round 7
// speedup vs baseline: 1.0717x; 1.0717x over previous
#include <cuda_runtime.h>

// QuantizedTopKSparsity == out[r,c] = rint( x[r,c] / (max_c |x[r,c]| + 1e-6) )
// (quantized values are in {-1,0,+1}; the top-k mask is an identity on x_q).
//
// Round-7: one row per CTA (16KB), 128 threads, 4 x 256-bit loads per thread
// front-batched -> 4KB in flight per warp (2x R5's MLP) while keeping CTAs
// small (R6 showed big CTAs kill DRAM%). evict_last loads / evict_first
// stores retained from the equal-best R5.

#define ROW_LEN 4096
#define THREADS 128
#define V8 4   // 4 x 8 floats = 32 floats per thread; 128*32 = 4096
#define NWARPS (THREADS / 32)

struct F8 { float a, b, c, d, e, f, g, h; };

__device__ __forceinline__ F8 ld_persist8(const void* p) {
    F8 v;
    asm volatile("ld.global.L2::evict_last.v8.b32 "
                 "{%0,%1,%2,%3,%4,%5,%6,%7}, [%8];"
                 : "=f"(v.a), "=f"(v.b), "=f"(v.c), "=f"(v.d),
                   "=f"(v.e), "=f"(v.f), "=f"(v.g), "=f"(v.h)
                 : "l"(p));
    return v;
}

__device__ __forceinline__ void st_stream8(void* p, const F8& v) {
    asm volatile("st.global.L2::evict_first.v8.b32 "
                 "[%0], {%1,%2,%3,%4,%5,%6,%7,%8};"
                 :: "l"(p),
                    "f"(v.a), "f"(v.b), "f"(v.c), "f"(v.d),
                    "f"(v.e), "f"(v.f), "f"(v.g), "f"(v.h)
                 : "memory");
}

__device__ __forceinline__ float absmax8(const F8& v) {
    float m0 = fmaxf(fmaxf(fabsf(v.a), fabsf(v.b)), fmaxf(fabsf(v.c), fabsf(v.d)));
    float m1 = fmaxf(fmaxf(fabsf(v.e), fabsf(v.f)), fmaxf(fabsf(v.g), fabsf(v.h)));
    return fmaxf(m0, m1);
}

__device__ __forceinline__ F8 quant8(const F8& v, float inv) {
    F8 o;
    o.a = rintf(v.a * inv); o.b = rintf(v.b * inv);
    o.c = rintf(v.c * inv); o.d = rintf(v.d * inv);
    o.e = rintf(v.e * inv); o.f = rintf(v.f * inv);
    o.g = rintf(v.g * inv); o.h = rintf(v.h * inv);
    return o;
}

__global__ __launch_bounds__(THREADS)
void qtopk_kernel(const float* __restrict__ x, float* __restrict__ out, int rows) {
    const int row = blockIdx.x;
    if (row >= rows) return;

    const float* __restrict__ xr = x   + (size_t)row * ROW_LEN;
    float* __restrict__ orr      = out + (size_t)row * ROW_LEN;

    const int t = threadIdx.x;

    // Front-batched 256-bit loads: 4 independent LDG.256 per thread in flight.
    F8 v[V8];
#pragma unroll
    for (int i = 0; i < V8; i++)
        v[i] = ld_persist8(xr + (t + i * THREADS) * 8);

    float m = 0.0f;
#pragma unroll
    for (int i = 0; i < V8; i++) m = fmaxf(m, absmax8(v[i]));

    // Warp absmax
#pragma unroll
    for (int o = 16; o > 0; o >>= 1)
        m = fmaxf(m, __shfl_xor_sync(0xffffffffu, m, o));

    // Cross-warp absmax via smem (4 warps)
    __shared__ float smax[NWARPS];
    if ((t & 31) == 0) smax[t >> 5] = m;
    __syncthreads();

    float g = smax[0];
#pragma unroll
    for (int w = 1; w < NWARPS; w++) g = fmaxf(g, smax[w]);

    const float inv = 1.0f / (g + 1e-6f);

#pragma unroll
    for (int i = 0; i < V8; i++)
        st_stream8(orr + (t + i * THREADS) * 8, quant8(v[i], inv));
}

extern "C" void kernel_launch(void* const* d_in, const int* in_sizes, int n_in,
                              void* d_out, int out_size) {
    const float* x = (const float*)d_in[0];
    float* out = (float*)d_out;
    const int rows = in_sizes[0] / ROW_LEN;   // 8192
    qtopk_kernel<<<rows, THREADS>>>(x, out, rows);
}

// round 8
// speedup vs baseline: 1.0780x; 1.0059x over previous
#include <cuda_runtime.h>

// QuantizedTopKSparsity == out[r,c] = rint( x[r,c] / (max_c |x[r,c]| + 1e-6) )
// (quantized values are in {-1,0,+1}; the top-k mask is an identity on x_q).
//
// Round-8: minimal-register / maximal-warp configuration. One row per CTA,
// 512 threads, exactly ONE 256-bit load and ONE 256-bit store per thread
// (512 * 8 floats = 4096 = row). ~24 regs -> occupancy can hit the full
// 2048 threads/SM. Streaming (evict_first) policy both directions.
// Measured trend R1(4x128b)=36.1 -> R5(2x256b)=35.1 ncu-us; this is the
// endpoint of that trend.

#define ROW_LEN 4096
#define THREADS 512
#define NWARPS (THREADS / 32)

struct F8 { float a, b, c, d, e, f, g, h; };

__device__ __forceinline__ F8 ld_stream8(const void* p) {
    F8 v;
    asm volatile("ld.global.L2::evict_first.v8.b32 "
                 "{%0,%1,%2,%3,%4,%5,%6,%7}, [%8];"
                 : "=f"(v.a), "=f"(v.b), "=f"(v.c), "=f"(v.d),
                   "=f"(v.e), "=f"(v.f), "=f"(v.g), "=f"(v.h)
                 : "l"(p));
    return v;
}

__device__ __forceinline__ void st_stream8(void* p, const F8& v) {
    asm volatile("st.global.L2::evict_first.v8.b32 "
                 "[%0], {%1,%2,%3,%4,%5,%6,%7,%8};"
                 :: "l"(p),
                    "f"(v.a), "f"(v.b), "f"(v.c), "f"(v.d),
                    "f"(v.e), "f"(v.f), "f"(v.g), "f"(v.h)
                 : "memory");
}

__global__ __launch_bounds__(THREADS)
void qtopk_kernel(const float* __restrict__ x, float* __restrict__ out, int rows) {
    const int row = blockIdx.x;
    if (row >= rows) return;

    const float* __restrict__ xr = x   + (size_t)row * ROW_LEN;
    float* __restrict__ orr      = out + (size_t)row * ROW_LEN;

    const int t = threadIdx.x;

    // Single 256-bit load per thread.
    F8 v = ld_stream8(xr + t * 8);

    float m0 = fmaxf(fmaxf(fabsf(v.a), fabsf(v.b)), fmaxf(fabsf(v.c), fabsf(v.d)));
    float m1 = fmaxf(fmaxf(fabsf(v.e), fabsf(v.f)), fmaxf(fabsf(v.g), fabsf(v.h)));
    float m  = fmaxf(m0, m1);

    // Warp absmax
#pragma unroll
    for (int o = 16; o > 0; o >>= 1)
        m = fmaxf(m, __shfl_xor_sync(0xffffffffu, m, o));

    // Cross-warp absmax via smem (16 warps)
    __shared__ float smax[NWARPS];
    if ((t & 31) == 0) smax[t >> 5] = m;
    __syncthreads();

    float g = smax[0];
#pragma unroll
    for (int w = 1; w < NWARPS; w++) g = fmaxf(g, smax[w]);

    const float inv = 1.0f / (g + 1e-6f);

    F8 o;
    o.a = rintf(v.a * inv); o.b = rintf(v.b * inv);
    o.c = rintf(v.c * inv); o.d = rintf(v.d * inv);
    o.e = rintf(v.e * inv); o.f = rintf(v.f * inv);
    o.g = rintf(v.g * inv); o.h = rintf(v.h * inv);

    // Single 256-bit store per thread.
    st_stream8(orr + t * 8, o);
}

extern "C" void kernel_launch(void* const* d_in, const int* in_sizes, int n_in,
                              void* d_out, int out_size) {
    const float* x = (const float*)d_in[0];
    float* out = (float*)d_out;
    const int rows = in_sizes[0] / ROW_LEN;   // 8192
    qtopk_kernel<<<rows, THREADS>>>(x, out, rows);
}